// round 14
// baseline (speedup 1.0000x reference)
#include <cuda_runtime.h>
#include <math.h>

#define Bn 128
#define Cn 48
#define Hn 64
#define Wn 64
#define Pn 32
#define OUT_ELEMS (Bn*Cn*Hn*Wn)

// Scratch (no allocations allowed)
__device__ unsigned long long g_M2[Cn*Cn];   // M duplicated (m,m) as f32x2
__device__ float4 g_S[256];                  // raw score sums per (b*2+g)

#define FMA2(acc, mm, vv) asm("fma.rn.f32x2 %0, %1, %2, %0;" : "+l"(acc) : "l"(mm), "l"(vv))
#define PACK2(dst, lo, hi) asm("mov.b64 %0, {%1,%2};" : "=l"(dst) : "f"(lo), "f"(hi))
#define UNPACK2(lo, hi, src) asm("mov.b64 {%0,%1}, %2;" : "=f"(lo), "=f"(hi) : "l"(src))

// ---------------------------------------------------------------------------
// Kernel A: prep. 8 blocks x 288 threads. Staging via 12 LDG.128 per thread,
// ALL issued before any STS (single latency exposure). 1 output per thread.
// ---------------------------------------------------------------------------
__global__ __launch_bounds__(288) void prep_kernel(
        const float* __restrict__ Wq1, const float* __restrict__ Wq2,
        const float* __restrict__ Wq3, const float* __restrict__ Wk1,
        const float* __restrict__ Wk2, const float* __restrict__ Wk3) {
    __shared__ float sW[6][Cn*Cn];   // 55296 B

    const int tid = threadIdx.x;     // 0..287 ; 576 float4 per matrix

    float4 v[12];
    v[0]  = ((const float4*)Wq1)[tid];  v[1]  = ((const float4*)Wq1)[tid + 288];
    v[2]  = ((const float4*)Wk1)[tid];  v[3]  = ((const float4*)Wk1)[tid + 288];
    v[4]  = ((const float4*)Wq2)[tid];  v[5]  = ((const float4*)Wq2)[tid + 288];
    v[6]  = ((const float4*)Wk2)[tid];  v[7]  = ((const float4*)Wk2)[tid + 288];
    v[8]  = ((const float4*)Wq3)[tid];  v[9]  = ((const float4*)Wq3)[tid + 288];
    v[10] = ((const float4*)Wk3)[tid];  v[11] = ((const float4*)Wk3)[tid + 288];
    #pragma unroll
    for (int m = 0; m < 6; ++m) {
        ((float4*)sW[m])[tid]       = v[m*2];
        ((float4*)sW[m])[tid + 288] = v[m*2 + 1];
    }
    __syncthreads();

    int w = blockIdx.x * 288 + tid;          // 0..2303
    int c = w / Cn, c2 = w % Cn;
    float s = 0.f;
    #pragma unroll
    for (int o = 0; o < Cn; ++o) {
        s += sW[0][o*Cn+c]*sW[1][o*Cn+c2]
           + sW[2][o*Cn+c]*sW[3][o*Cn+c2]
           + sW[4][o*Cn+c]*sW[5][o*Cn+c2];
    }
    s *= (1.0f / sqrtf((float)(Cn*Pn*Pn)));
    ((float2*)g_M2)[w] = make_float2(s, s);
}

// ---------------------------------------------------------------------------
// Kernel B: FUSED score + softmax + output. 256 CTAs x 256 threads.
// CTA = (b, g). Lane kl owns k = {2kl, 2kl+1, 64+2kl, 64+2kl+1} so the v
// loads are 2x LDS.128 (half the LSU instructions of 4x LDS.64).
// ---------------------------------------------------------------------------
__global__ __launch_bounds__(256, 2) void fused_kernel(
        const float* __restrict__ x,
        const float* __restrict__ off1p, const float* __restrict__ off2p,
        const float* __restrict__ off3p,
        float* __restrict__ out) {
    __shared__ __align__(16) unsigned long long sV[Cn*128];   // 49152 B  [c][k]
    __shared__ unsigned long long sM2[Cn*Cn];                 // 18432 B
    __shared__ float4 sred[8];
    __shared__ float sc[4];

    const int bid = blockIdx.x;
    const int g = bid & 1;
    const int b = bid >> 1;
    const int tid = threadIdx.x;
    const int ci = tid >> 5;
    const int kl = tid & 31;

    // M staging: batched (9 loads in flight, then 9 stores)
    {
        unsigned long long m[9];
        #pragma unroll
        for (int k = 0; k < 9; ++k) m[k] = g_M2[tid + k*256];
        #pragma unroll
        for (int k = 0; k < 9; ++k) sM2[tid + k*256] = m[k];
    }

    const float2* xb2 = (const float2*)(x + (size_t)b * Cn * Hn * Wn);

    float p00 = 0.f, p01 = 0.f, p10 = 0.f, p11 = 0.f;

    for (int kq = 0; kq < 4; ++kq) {
        __syncthreads();   // previous epilogue readers done before sV overwrite
        // V staging: 24 entries/thread in 3 batches of 8
        #pragma unroll
        for (int bt = 0; bt < 3; ++bt) {
            float2 ra[8], rb[8];
            #pragma unroll
            for (int k = 0; k < 8; ++k) {
                int idx = tid + (bt*8 + k)*256;
                int c2 = idx >> 7;
                int kk = idx & 127;
                int yy = kk >> 4;
                int xx = kk & 15;
                int yt = kq*8 + yy;
                ra[k] = xb2[((size_t)c2*Hn + yt)*32      + g*16 + xx];
                rb[k] = xb2[((size_t)c2*Hn + yt + 32)*32 + g*16 + xx];
            }
            #pragma unroll
            for (int k = 0; k < 8; ++k) {
                int idx = tid + (bt*8 + k)*256;
                unsigned long long pk;
                if (g == 0) PACK2(pk, ra[k].x, rb[k].x);
                else        PACK2(pk, ra[k].y, rb[k].y);
                sV[idx] = pk;
            }
        }
        __syncthreads();

        unsigned long long acc[24];
        #pragma unroll
        for (int i = 0; i < 24; ++i) acc[i] = 0ULL;

        #pragma unroll
        for (int c2 = 0; c2 < Cn; ++c2) {
            ulonglong2 va = *(const ulonglong2*)&sV[c2*128 + 2*kl];
            ulonglong2 vb = *(const ulonglong2*)&sV[c2*128 + 64 + 2*kl];
            #pragma unroll
            for (int r = 0; r < 6; ++r) {
                unsigned long long m = sM2[(ci*6 + r)*Cn + c2];   // broadcast
                FMA2(acc[r*4    ], m, va.x);
                FMA2(acc[r*4 + 1], m, va.y);
                FMA2(acc[r*4 + 2], m, vb.x);
                FMA2(acc[r*4 + 3], m, vb.y);
            }
        }

        #pragma unroll
        for (int r = 0; r < 6; ++r) {
            ulonglong2 va = *(const ulonglong2*)&sV[(ci*6 + r)*128 + 2*kl];
            ulonglong2 vb = *(const ulonglong2*)&sV[(ci*6 + r)*128 + 64 + 2*kl];
            unsigned long long vv[4] = {va.x, va.y, vb.x, vb.y};
            #pragma unroll
            for (int j = 0; j < 4; ++j) {
                float wt, wb, vt, vbo;
                UNPACK2(wt, wb, acc[r*4 + j]);
                UNPACK2(vt, vbo, vv[j]);
                p00 = fmaf(vt, wt, p00);   p01 = fmaf(vt, wb, p01);
                p10 = fmaf(vbo, wt, p10);  p11 = fmaf(vbo, wb, p11);
            }
        }
    }

    // reduce p across the block (deterministic)
    #pragma unroll
    for (int off = 16; off; off >>= 1) {
        p00 += __shfl_xor_sync(0xffffffffu, p00, off);
        p01 += __shfl_xor_sync(0xffffffffu, p01, off);
        p10 += __shfl_xor_sync(0xffffffffu, p10, off);
        p11 += __shfl_xor_sync(0xffffffffu, p11, off);
    }
    if (kl == 0) sred[ci] = make_float4(p00, p01, p10, p11);
    __syncthreads();
    if (tid == 0) {
        float4 sv = sred[0];
        #pragma unroll
        for (int w = 1; w < 8; ++w) {
            float4 t = sred[w];
            sv.x += t.x; sv.y += t.y; sv.z += t.z; sv.w += t.w;
        }
        g_S[bid] = sv;                       // raw sums for the logdet kernel

        const float off  = off1p[0];
        const float off2 = off2p[0];
        const float off3 = off3p[0];
        float stt = sv.x + off3, stb = sv.y + off3;
        float sbt = sv.z + off3, sbb = sv.w + off3;
        float z = off3;

        float mx  = fmaxf(fmaxf(stt, stb), z);
        float e0  = expf(stt-mx), e1 = expf(stb-mx), ez = expf(z-mx);
        float inv = 1.f / (e0 + e1 + 2.f*ez);
        sc[0] = e0*inv + off2 + off;         // a_tt
        sc[1] = e1*inv + off2;               // a_tb

        mx  = fmaxf(fmaxf(sbt, sbb), z);
        e0  = expf(sbt-mx); e1 = expf(sbb-mx); ez = expf(z-mx);
        inv = 1.f / (e0 + e1 + 2.f*ez);
        sc[2] = e0*inv + off2;               // a_bt
        sc[3] = e1*inv + off2 + off;         // a_bb
    }
    __syncthreads();

    // ---- Phase 2: output for (b, column-block g) ----
    const float a_tt = sc[0], a_tb = sc[1], a_bt = sc[2], a_bb = sc[3];
    const float4* xp = (const float4*)(x + (size_t)b * Cn * Hn * Wn);
    float4* op = (float4*)(out + (size_t)b * Cn * Hn * Wn);

    #pragma unroll 4
    for (int i = 0; i < 48; ++i) {
        int idx = tid + i*256;               // 12288 float4-pairs
        int x4l = idx & 7;
        int y   = (idx >> 3) & 31;
        int c   = idx >> 8;
        int fo  = (c*Hn + y)*16 + g*8 + x4l; // float4 offset
        float4 xt = xp[fo];
        float4 xb = xp[fo + 32*16];
        float4 ot, ob;
        if (g == 0) {  // pass-through at even columns (x,z)
            ot.x = xt.x;                    ob.x = xb.x;
            ot.y = a_tt*xt.y + a_tb*xb.y;   ob.y = a_bt*xt.y + a_bb*xb.y;
            ot.z = xt.z;                    ob.z = xb.z;
            ot.w = a_tt*xt.w + a_tb*xb.w;   ob.w = a_bt*xt.w + a_bb*xb.w;
        } else {       // pass-through at odd columns (y,w)
            ot.x = a_tt*xt.x + a_tb*xb.x;   ob.x = a_bt*xt.x + a_bb*xb.x;
            ot.y = xt.y;                    ob.y = xb.y;
            ot.z = a_tt*xt.z + a_tb*xb.z;   ob.z = a_bt*xt.z + a_bb*xb.z;
            ot.w = xt.w;                    ob.w = xb.w;
        }
        __stwt(&op[fo], ot);
        __stwt(&op[fo + 32*16], ob);
    }
}

// ---------------------------------------------------------------------------
// Kernel C: logdet from raw score sums (needs both g of each b).
// ---------------------------------------------------------------------------
__global__ void logdet_kernel(const float* __restrict__ logdet_in,
                              const float* __restrict__ off1p,
                              const float* __restrict__ off2p,
                              const float* __restrict__ off3p,
                              float* __restrict__ out, int out_size) {
    int b = threadIdx.x;
    if (b >= Bn) return;
    const float off  = off1p[0];
    const float off2 = off2p[0];
    const float off3 = off3p[0];
    float ld = logdet_in[b];

    #pragma unroll
    for (int g = 0; g < 2; ++g) {
        float4 s = g_S[b*2 + g];
        float stt = s.x + off3, stb = s.y + off3;
        float sbt = s.z + off3, sbb = s.w + off3;
        float z = off3;

        float mx   = fmaxf(fmaxf(stt, stb), z);
        float e0   = expf(stt-mx), e1 = expf(stb-mx), ez = expf(z-mx);
        float inv  = 1.f / (e0 + e1 + 2.f*ez);
        float a_tt = e0*inv + off2 + off;
        float a_tb = e1*inv + off2;

        mx  = fmaxf(fmaxf(sbt, sbb), z);
        e0  = expf(sbt-mx); e1 = expf(sbb-mx); ez = expf(z-mx);
        inv = 1.f / (e0 + e1 + 2.f*ez);
        float a_bt = e0*inv + off2;
        float a_bb = e1*inv + off2 + off;

        float det = a_tt*a_bb - a_tb*a_bt;
        ld += logf(fabsf(det)) * (float)(Pn*(Pn/2)*Cn);
    }
    if (OUT_ELEMS + b < out_size) out[OUT_ELEMS + b] = ld;
}

// ---------------------------------------------------------------------------
extern "C" void kernel_launch(void* const* d_in, const int* in_sizes, int n_in,
                              void* d_out, int out_size) {
    const float* x      = (const float*)d_in[0];
    const float* logdet = (const float*)d_in[1];
    const float* Wq1    = (const float*)d_in[2];
    const float* Wq2    = (const float*)d_in[3];
    const float* Wq3    = (const float*)d_in[4];
    const float* Wk1    = (const float*)d_in[5];
    const float* Wk2    = (const float*)d_in[6];
    const float* Wk3    = (const float*)d_in[7];
    const float* off1   = (const float*)d_in[8];
    const float* off2   = (const float*)d_in[9];
    const float* off3   = (const float*)d_in[10];
    float* out = (float*)d_out;

    prep_kernel<<<8, 288>>>(Wq1, Wq2, Wq3, Wk1, Wk2, Wk3);
    fused_kernel<<<256, 256>>>(x, off1, off2, off3, out);
    logdet_kernel<<<1, 128>>>(logdet, off1, off2, off3, out, out_size);
}

// round 15
// speedup vs baseline: 1.0036x; 1.0036x over previous
#include <cuda_runtime.h>
#include <math.h>

#define Bn 128
#define Cn 48
#define Hn 64
#define Wn 64
#define Pn 32
#define OUT_ELEMS (Bn*Cn*Hn*Wn)

// Scratch (no allocations allowed)
__device__ unsigned long long g_M2[Cn*Cn];   // M duplicated (m,m) as f32x2
__device__ float4 g_S[256];                  // raw score sums per (b*2+g)
__device__ int g_flag;                       // M-ready arrivals (reset by logdet)

#define FMA2(acc, mm, vv) asm("fma.rn.f32x2 %0, %1, %2, %0;" : "+l"(acc) : "l"(mm), "l"(vv))
#define PACK2(dst, lo, hi) asm("mov.b64 %0, {%1,%2};" : "=l"(dst) : "f"(lo), "f"(hi))
#define UNPACK2(lo, hi, src) asm("mov.b64 {%0,%1}, %2;" : "=f"(lo), "=f"(hi) : "l"(src))

// ---------------------------------------------------------------------------
// Kernel A: FUSED prep + score + softmax + output. 256 CTAs x 256 threads.
// CTA = (b, g). CTAs 0..8 additionally compute M (256 entries each) while the
// rest stage V; a flag handshake orders M before the score mainloop.
// ---------------------------------------------------------------------------
__global__ __launch_bounds__(256, 2) void fused_kernel(
        const float* __restrict__ x,
        const float* __restrict__ Wq1, const float* __restrict__ Wq2,
        const float* __restrict__ Wq3, const float* __restrict__ Wk1,
        const float* __restrict__ Wk2, const float* __restrict__ Wk3,
        const float* __restrict__ off1p, const float* __restrict__ off2p,
        const float* __restrict__ off3p,
        float* __restrict__ out) {
    __shared__ unsigned long long sV[Cn*128];   // 49152 B  [c][k]
    __shared__ unsigned long long sM2[Cn*Cn];   // 18432 B
    __shared__ float4 sred[8];
    __shared__ float sc[4];

    const int bid = blockIdx.x;
    const int g = bid & 1;
    const int b = bid >> 1;
    const int tid = threadIdx.x;
    const int ci = tid >> 5;
    const int kl = tid & 31;

    // ---- M producers: CTAs 0..8, one entry per thread, direct L2 ldg ----
    if (bid < 9) {
        int e  = bid*256 + tid;                // 0..2303
        int c  = e / Cn, c2 = e % Cn;
        float s = 0.f;
        #pragma unroll
        for (int o = 0; o < Cn; ++o) {
            s += __ldg(&Wq1[o*Cn+c])*__ldg(&Wk1[o*Cn+c2])
               + __ldg(&Wq2[o*Cn+c])*__ldg(&Wk2[o*Cn+c2])
               + __ldg(&Wq3[o*Cn+c])*__ldg(&Wk3[o*Cn+c2]);
        }
        s *= (1.0f / sqrtf((float)(Cn*Pn*Pn)));
        ((float2*)g_M2)[e] = make_float2(s, s);
        __threadfence();
        __syncthreads();
        if (tid == 0) atomicAdd(&g_flag, 1);
    }

    const float2* xb2 = (const float2*)(x + (size_t)b * Cn * Hn * Wn);

    // ---- V staging for kq=0 (independent of M) ----
    #pragma unroll
    for (int bt = 0; bt < 3; ++bt) {
        float2 ra[8], rb[8];
        #pragma unroll
        for (int k = 0; k < 8; ++k) {
            int idx = tid + (bt*8 + k)*256;
            int c2 = idx >> 7;
            int kk = idx & 127;
            int yy = kk >> 4;
            int xx = kk & 15;
            ra[k] = xb2[((size_t)c2*Hn + yy)*32      + g*16 + xx];
            rb[k] = xb2[((size_t)c2*Hn + yy + 32)*32 + g*16 + xx];
        }
        #pragma unroll
        for (int k = 0; k < 8; ++k) {
            int idx = tid + (bt*8 + k)*256;
            unsigned long long pk;
            if (g == 0) PACK2(pk, ra[k].x, rb[k].x);
            else        PACK2(pk, ra[k].y, rb[k].y);
            sV[idx] = pk;
        }
    }

    // ---- wait for M, then load it to smem ----
    if (tid == 0) {
        while (atomicAdd(&g_flag, 0) < 9) { }
    }
    __syncthreads();
    __threadfence();
    {
        unsigned long long m[9];
        #pragma unroll
        for (int k = 0; k < 9; ++k) m[k] = g_M2[tid + k*256];
        #pragma unroll
        for (int k = 0; k < 9; ++k) sM2[tid + k*256] = m[k];
    }

    float p00 = 0.f, p01 = 0.f, p10 = 0.f, p11 = 0.f;

    for (int kq = 0; kq < 4; ++kq) {
        __syncthreads();   // staged sV (and sM2 on kq=0) visible to all

        unsigned long long acc[24];
        #pragma unroll
        for (int i = 0; i < 24; ++i) acc[i] = 0ULL;

        #pragma unroll
        for (int c2 = 0; c2 < Cn; ++c2) {
            unsigned long long v0 = sV[c2*128 + kl];
            unsigned long long v1 = sV[c2*128 + kl + 32];
            unsigned long long v2 = sV[c2*128 + kl + 64];
            unsigned long long v3 = sV[c2*128 + kl + 96];
            #pragma unroll
            for (int r = 0; r < 6; ++r) {
                unsigned long long m = sM2[(ci*6 + r)*Cn + c2];   // broadcast
                FMA2(acc[r*4    ], m, v0);
                FMA2(acc[r*4 + 1], m, v1);
                FMA2(acc[r*4 + 2], m, v2);
                FMA2(acc[r*4 + 3], m, v3);
            }
        }

        #pragma unroll
        for (int r = 0; r < 6; ++r) {
            #pragma unroll
            for (int j = 0; j < 4; ++j) {
                float wt, wb, vt, vb;
                UNPACK2(wt, wb, acc[r*4 + j]);
                unsigned long long v = sV[(ci*6 + r)*128 + kl + j*32];
                UNPACK2(vt, vb, v);
                p00 = fmaf(vt, wt, p00);  p01 = fmaf(vt, wb, p01);
                p10 = fmaf(vb, wt, p10);  p11 = fmaf(vb, wb, p11);
            }
        }

        if (kq < 3) {
            __syncthreads();   // all readers of sV done before restage
            int kqn = kq + 1;
            #pragma unroll
            for (int bt = 0; bt < 3; ++bt) {
                float2 ra[8], rb[8];
                #pragma unroll
                for (int k = 0; k < 8; ++k) {
                    int idx = tid + (bt*8 + k)*256;
                    int c2 = idx >> 7;
                    int kk = idx & 127;
                    int yy = kk >> 4;
                    int xx = kk & 15;
                    int yt = kqn*8 + yy;
                    ra[k] = xb2[((size_t)c2*Hn + yt)*32      + g*16 + xx];
                    rb[k] = xb2[((size_t)c2*Hn + yt + 32)*32 + g*16 + xx];
                }
                #pragma unroll
                for (int k = 0; k < 8; ++k) {
                    int idx = tid + (bt*8 + k)*256;
                    unsigned long long pk;
                    if (g == 0) PACK2(pk, ra[k].x, rb[k].x);
                    else        PACK2(pk, ra[k].y, rb[k].y);
                    sV[idx] = pk;
                }
            }
        }
    }

    // reduce p across the block (deterministic)
    #pragma unroll
    for (int off = 16; off; off >>= 1) {
        p00 += __shfl_xor_sync(0xffffffffu, p00, off);
        p01 += __shfl_xor_sync(0xffffffffu, p01, off);
        p10 += __shfl_xor_sync(0xffffffffu, p10, off);
        p11 += __shfl_xor_sync(0xffffffffu, p11, off);
    }
    if (kl == 0) sred[ci] = make_float4(p00, p01, p10, p11);
    __syncthreads();
    if (tid == 0) {
        float4 sv = sred[0];
        #pragma unroll
        for (int w = 1; w < 8; ++w) {
            float4 t = sred[w];
            sv.x += t.x; sv.y += t.y; sv.z += t.z; sv.w += t.w;
        }
        g_S[bid] = sv;                       // raw sums for the logdet kernel

        const float off  = off1p[0];
        const float off2 = off2p[0];
        const float off3 = off3p[0];
        float stt = sv.x + off3, stb = sv.y + off3;
        float sbt = sv.z + off3, sbb = sv.w + off3;
        float z = off3;

        float mx  = fmaxf(fmaxf(stt, stb), z);
        float e0  = expf(stt-mx), e1 = expf(stb-mx), ez = expf(z-mx);
        float inv = 1.f / (e0 + e1 + 2.f*ez);
        sc[0] = e0*inv + off2 + off;         // a_tt
        sc[1] = e1*inv + off2;               // a_tb

        mx  = fmaxf(fmaxf(sbt, sbb), z);
        e0  = expf(sbt-mx); e1 = expf(sbb-mx); ez = expf(z-mx);
        inv = 1.f / (e0 + e1 + 2.f*ez);
        sc[2] = e0*inv + off2;               // a_bt
        sc[3] = e1*inv + off2 + off;         // a_bb
    }
    __syncthreads();

    // ---- Phase 2: output for (b, column-block g) ----
    const float a_tt = sc[0], a_tb = sc[1], a_bt = sc[2], a_bb = sc[3];
    const float4* xp = (const float4*)(x + (size_t)b * Cn * Hn * Wn);
    float4* op = (float4*)(out + (size_t)b * Cn * Hn * Wn);

    #pragma unroll 4
    for (int i = 0; i < 48; ++i) {
        int idx = tid + i*256;               // 12288 float4-pairs
        int x4l = idx & 7;
        int y   = (idx >> 3) & 31;
        int c   = idx >> 8;
        int fo  = (c*Hn + y)*16 + g*8 + x4l; // float4 offset
        float4 xt = xp[fo];
        float4 xb = xp[fo + 32*16];
        float4 ot, ob;
        if (g == 0) {  // pass-through at even columns (x,z)
            ot.x = xt.x;                    ob.x = xb.x;
            ot.y = a_tt*xt.y + a_tb*xb.y;   ob.y = a_bt*xt.y + a_bb*xb.y;
            ot.z = xt.z;                    ob.z = xb.z;
            ot.w = a_tt*xt.w + a_tb*xb.w;   ob.w = a_bt*xt.w + a_bb*xb.w;
        } else {       // pass-through at odd columns (y,w)
            ot.x = a_tt*xt.x + a_tb*xb.x;   ob.x = a_bt*xt.x + a_bb*xb.x;
            ot.y = xt.y;                    ob.y = xb.y;
            ot.z = a_tt*xt.z + a_tb*xb.z;   ob.z = a_bt*xt.z + a_bb*xb.z;
            ot.w = xt.w;                    ob.w = xb.w;
        }
        __stwt(&op[fo], ot);
        __stwt(&op[fo + 32*16], ob);
    }
}

// ---------------------------------------------------------------------------
// Kernel B: logdet from raw score sums; also resets the M flag for the next
// launch (stream-ordered after all fused CTAs).
// ---------------------------------------------------------------------------
__global__ void logdet_kernel(const float* __restrict__ logdet_in,
                              const float* __restrict__ off1p,
                              const float* __restrict__ off2p,
                              const float* __restrict__ off3p,
                              float* __restrict__ out, int out_size) {
    int b = threadIdx.x;
    if (b == 0) g_flag = 0;                  // reset handshake for next launch
    if (b >= Bn) return;
    const float off  = off1p[0];
    const float off2 = off2p[0];
    const float off3 = off3p[0];
    float ld = logdet_in[b];

    #pragma unroll
    for (int g = 0; g < 2; ++g) {
        float4 s = g_S[b*2 + g];
        float stt = s.x + off3, stb = s.y + off3;
        float sbt = s.z + off3, sbb = s.w + off3;
        float z = off3;

        float mx   = fmaxf(fmaxf(stt, stb), z);
        float e0   = expf(stt-mx), e1 = expf(stb-mx), ez = expf(z-mx);
        float inv  = 1.f / (e0 + e1 + 2.f*ez);
        float a_tt = e0*inv + off2 + off;
        float a_tb = e1*inv + off2;

        mx  = fmaxf(fmaxf(sbt, sbb), z);
        e0  = expf(sbt-mx); e1 = expf(sbb-mx); ez = expf(z-mx);
        inv = 1.f / (e0 + e1 + 2.f*ez);
        float a_bt = e0*inv + off2;
        float a_bb = e1*inv + off2 + off;

        float det = a_tt*a_bb - a_tb*a_bt;
        ld += logf(fabsf(det)) * (float)(Pn*(Pn/2)*Cn);
    }
    if (OUT_ELEMS + b < out_size) out[OUT_ELEMS + b] = ld;
}

// ---------------------------------------------------------------------------
extern "C" void kernel_launch(void* const* d_in, const int* in_sizes, int n_in,
                              void* d_out, int out_size) {
    const float* x      = (const float*)d_in[0];
    const float* logdet = (const float*)d_in[1];
    const float* Wq1    = (const float*)d_in[2];
    const float* Wq2    = (const float*)d_in[3];
    const float* Wq3    = (const float*)d_in[4];
    const float* Wk1    = (const float*)d_in[5];
    const float* Wk2    = (const float*)d_in[6];
    const float* Wk3    = (const float*)d_in[7];
    const float* off1   = (const float*)d_in[8];
    const float* off2   = (const float*)d_in[9];
    const float* off3   = (const float*)d_in[10];
    float* out = (float*)d_out;

    fused_kernel<<<256, 256>>>(x, Wq1, Wq2, Wq3, Wk1, Wk2, Wk3,
                               off1, off2, off3, out);
    logdet_kernel<<<1, 128>>>(logdet, off1, off2, off3, out, out_size);
}

// round 16
// speedup vs baseline: 1.0199x; 1.0162x over previous
#include <cuda_runtime.h>
#include <math.h>

#define Bn 128
#define Cn 48
#define Hn 64
#define Wn 64
#define Pn 32
#define OUT_ELEMS (Bn*Cn*Hn*Wn)

// Scratch (no allocations allowed)
__device__ unsigned long long g_M2[Cn*Cn];   // M duplicated (m,m) as f32x2
__device__ float4 g_S[256];                  // raw score sums per (b*2+g)
__device__ int g_flag;                       // M-ready arrivals
__device__ int g_done;                       // phase-2 completion arrivals

#define FMA2(acc, mm, vv) asm("fma.rn.f32x2 %0, %1, %2, %0;" : "+l"(acc) : "l"(mm), "l"(vv))
#define PACK2(dst, lo, hi) asm("mov.b64 %0, {%1,%2};" : "=l"(dst) : "f"(lo), "f"(hi))
#define UNPACK2(lo, hi, src) asm("mov.b64 {%0,%1}, %2;" : "=f"(lo), "=f"(hi) : "l"(src))

// ---------------------------------------------------------------------------
// SINGLE FUSED KERNEL: prep(M) + score + softmax + output + logdet.
// 256 CTAs x 256 threads, CTA = (b, g), occ 2 (all CTAs co-resident).
// CTAs 0..8: stage W in smem (batched LDG.128), compute M fast, flag.
// All CTAs: stage V(kq=0), wait flag, mainloop, softmax, phase-2 output.
// Last CTA (arrival counter): logdet for all b + flag resets for next replay.
// ---------------------------------------------------------------------------
__global__ __launch_bounds__(256, 2) void fused_kernel(
        const float* __restrict__ x,
        const float* __restrict__ logdet_in,
        const float* __restrict__ Wq1, const float* __restrict__ Wq2,
        const float* __restrict__ Wq3, const float* __restrict__ Wk1,
        const float* __restrict__ Wk2, const float* __restrict__ Wk3,
        const float* __restrict__ off1p, const float* __restrict__ off2p,
        const float* __restrict__ off3p,
        float* __restrict__ out, int out_size) {
    __shared__ unsigned long long sV[Cn*128];   // 49152 B  [c][k]  (union: W mats 0..4)
    __shared__ unsigned long long sM2[Cn*Cn];   // 18432 B          (union: W mat 5)
    __shared__ float4 sred[8];
    __shared__ float sc[4];
    __shared__ int s_last;

    const int bid = blockIdx.x;
    const int g = bid & 1;
    const int b = bid >> 1;
    const int tid = threadIdx.x;
    const int ci = tid >> 5;
    const int kl = tid & 31;

    // ---- M producers: CTAs 0..8 ----
    if (bid < 9) {
        float* swA = (float*)sV;     // matrices 0..4 (5*9216 B = 46080 <= 49152)
        float* swB = (float*)sM2;    // matrix 5 (9216 B)
        // stage: 3456 float4 total, 14 batched loads/thread (warp-uniform m)
        float4 regs[14];
        #pragma unroll
        for (int k = 0; k < 14; ++k) {
            int idx = tid + k*256;
            if (idx < 3456) {
                int m = idx / 576, off = idx % 576;
                const float4* p;
                switch (m) {
                    case 0:  p = (const float4*)Wq1; break;
                    case 1:  p = (const float4*)Wk1; break;
                    case 2:  p = (const float4*)Wq2; break;
                    case 3:  p = (const float4*)Wk2; break;
                    case 4:  p = (const float4*)Wq3; break;
                    default: p = (const float4*)Wk3; break;
                }
                regs[k] = p[off];
            }
        }
        #pragma unroll
        for (int k = 0; k < 14; ++k) {
            int idx = tid + k*256;
            if (idx < 3456) {
                int m = idx / 576, off = idx % 576;
                float* dst = (m < 5) ? (swA + m*2304 + off*4) : (swB + off*4);
                float4 v = regs[k];
                dst[0]=v.x; dst[1]=v.y; dst[2]=v.z; dst[3]=v.w;
            }
        }
        __syncthreads();
        // compute 1 entry/thread from smem
        int e = bid*256 + tid;                 // 0..2303
        int c = e / Cn, c2 = e % Cn;
        float s = 0.f;
        #pragma unroll
        for (int o = 0; o < Cn; ++o) {
            s += swA[0*2304 + o*Cn + c]*swA[1*2304 + o*Cn + c2]
               + swA[2*2304 + o*Cn + c]*swA[3*2304 + o*Cn + c2]
               + swA[4*2304 + o*Cn + c]*swB[o*Cn + c2];
        }
        s *= (1.0f / sqrtf((float)(Cn*Pn*Pn)));
        ((float2*)g_M2)[e] = make_float2(s, s);
        __threadfence();
        __syncthreads();                       // all writes done; sV/sM2 reusable
        if (tid == 0) atomicAdd(&g_flag, 1);
    }

    const float2* xb2 = (const float2*)(x + (size_t)b * Cn * Hn * Wn);

    // ---- V staging for kq=0 (independent of M) ----
    #pragma unroll
    for (int bt = 0; bt < 3; ++bt) {
        float2 ra[8], rb[8];
        #pragma unroll
        for (int k = 0; k < 8; ++k) {
            int idx = tid + (bt*8 + k)*256;
            int c2 = idx >> 7;
            int kk = idx & 127;
            int yy = kk >> 4;
            int xx = kk & 15;
            ra[k] = xb2[((size_t)c2*Hn + yy)*32      + g*16 + xx];
            rb[k] = xb2[((size_t)c2*Hn + yy + 32)*32 + g*16 + xx];
        }
        #pragma unroll
        for (int k = 0; k < 8; ++k) {
            int idx = tid + (bt*8 + k)*256;
            unsigned long long pk;
            if (g == 0) PACK2(pk, ra[k].x, rb[k].x);
            else        PACK2(pk, ra[k].y, rb[k].y);
            sV[idx] = pk;
        }
    }

    // ---- wait for M, then load it to smem ----
    if (tid == 0) {
        while (atomicAdd(&g_flag, 0) < 9) { }
    }
    __syncthreads();
    __threadfence();
    {
        unsigned long long m[9];
        #pragma unroll
        for (int k = 0; k < 9; ++k) m[k] = g_M2[tid + k*256];
        #pragma unroll
        for (int k = 0; k < 9; ++k) sM2[tid + k*256] = m[k];
    }

    float p00 = 0.f, p01 = 0.f, p10 = 0.f, p11 = 0.f;

    for (int kq = 0; kq < 4; ++kq) {
        __syncthreads();   // staged sV (and sM2 on kq=0) visible to all

        unsigned long long acc[24];
        #pragma unroll
        for (int i = 0; i < 24; ++i) acc[i] = 0ULL;

        #pragma unroll
        for (int c2 = 0; c2 < Cn; ++c2) {
            unsigned long long v0 = sV[c2*128 + kl];
            unsigned long long v1 = sV[c2*128 + kl + 32];
            unsigned long long v2 = sV[c2*128 + kl + 64];
            unsigned long long v3 = sV[c2*128 + kl + 96];
            #pragma unroll
            for (int r = 0; r < 6; ++r) {
                unsigned long long m = sM2[(ci*6 + r)*Cn + c2];   // broadcast
                FMA2(acc[r*4    ], m, v0);
                FMA2(acc[r*4 + 1], m, v1);
                FMA2(acc[r*4 + 2], m, v2);
                FMA2(acc[r*4 + 3], m, v3);
            }
        }

        #pragma unroll
        for (int r = 0; r < 6; ++r) {
            #pragma unroll
            for (int j = 0; j < 4; ++j) {
                float wt, wb, vt, vb;
                UNPACK2(wt, wb, acc[r*4 + j]);
                unsigned long long v = sV[(ci*6 + r)*128 + kl + j*32];
                UNPACK2(vt, vb, v);
                p00 = fmaf(vt, wt, p00);  p01 = fmaf(vt, wb, p01);
                p10 = fmaf(vb, wt, p10);  p11 = fmaf(vb, wb, p11);
            }
        }

        if (kq < 3) {
            __syncthreads();   // all readers of sV done before restage
            int kqn = kq + 1;
            #pragma unroll
            for (int bt = 0; bt < 3; ++bt) {
                float2 ra[8], rb[8];
                #pragma unroll
                for (int k = 0; k < 8; ++k) {
                    int idx = tid + (bt*8 + k)*256;
                    int c2 = idx >> 7;
                    int kk = idx & 127;
                    int yy = kk >> 4;
                    int xx = kk & 15;
                    int yt = kqn*8 + yy;
                    ra[k] = xb2[((size_t)c2*Hn + yt)*32      + g*16 + xx];
                    rb[k] = xb2[((size_t)c2*Hn + yt + 32)*32 + g*16 + xx];
                }
                #pragma unroll
                for (int k = 0; k < 8; ++k) {
                    int idx = tid + (bt*8 + k)*256;
                    unsigned long long pk;
                    if (g == 0) PACK2(pk, ra[k].x, rb[k].x);
                    else        PACK2(pk, ra[k].y, rb[k].y);
                    sV[idx] = pk;
                }
            }
        }
    }

    // reduce p across the block (deterministic)
    #pragma unroll
    for (int off = 16; off; off >>= 1) {
        p00 += __shfl_xor_sync(0xffffffffu, p00, off);
        p01 += __shfl_xor_sync(0xffffffffu, p01, off);
        p10 += __shfl_xor_sync(0xffffffffu, p10, off);
        p11 += __shfl_xor_sync(0xffffffffu, p11, off);
    }
    if (kl == 0) sred[ci] = make_float4(p00, p01, p10, p11);
    __syncthreads();
    if (tid == 0) {
        float4 sv = sred[0];
        #pragma unroll
        for (int w = 1; w < 8; ++w) {
            float4 t = sred[w];
            sv.x += t.x; sv.y += t.y; sv.z += t.z; sv.w += t.w;
        }
        g_S[bid] = sv;                       // raw sums for the logdet tail

        const float off  = off1p[0];
        const float off2 = off2p[0];
        const float off3 = off3p[0];
        float stt = sv.x + off3, stb = sv.y + off3;
        float sbt = sv.z + off3, sbb = sv.w + off3;
        float z = off3;

        float mx  = fmaxf(fmaxf(stt, stb), z);
        float e0  = expf(stt-mx), e1 = expf(stb-mx), ez = expf(z-mx);
        float inv = 1.f / (e0 + e1 + 2.f*ez);
        sc[0] = e0*inv + off2 + off;         // a_tt
        sc[1] = e1*inv + off2;               // a_tb

        mx  = fmaxf(fmaxf(sbt, sbb), z);
        e0  = expf(sbt-mx); e1 = expf(sbb-mx); ez = expf(z-mx);
        inv = 1.f / (e0 + e1 + 2.f*ez);
        sc[2] = e0*inv + off2;               // a_bt
        sc[3] = e1*inv + off2 + off;         // a_bb
    }
    __syncthreads();

    // ---- Phase 2: output for (b, column-block g) ----
    const float a_tt = sc[0], a_tb = sc[1], a_bt = sc[2], a_bb = sc[3];
    const float4* xp = (const float4*)(x + (size_t)b * Cn * Hn * Wn);
    float4* op = (float4*)(out + (size_t)b * Cn * Hn * Wn);

    #pragma unroll 4
    for (int i = 0; i < 48; ++i) {
        int idx = tid + i*256;               // 12288 float4-pairs
        int x4l = idx & 7;
        int y   = (idx >> 3) & 31;
        int c   = idx >> 8;
        int fo  = (c*Hn + y)*16 + g*8 + x4l; // float4 offset
        float4 xt = xp[fo];
        float4 xb = xp[fo + 32*16];
        float4 ot, ob;
        if (g == 0) {  // pass-through at even columns (x,z)
            ot.x = xt.x;                    ob.x = xb.x;
            ot.y = a_tt*xt.y + a_tb*xb.y;   ob.y = a_bt*xt.y + a_bb*xb.y;
            ot.z = xt.z;                    ob.z = xb.z;
            ot.w = a_tt*xt.w + a_tb*xb.w;   ob.w = a_bt*xt.w + a_bb*xb.w;
        } else {       // pass-through at odd columns (y,w)
            ot.x = a_tt*xt.x + a_tb*xb.x;   ob.x = a_bt*xt.x + a_bb*xb.x;
            ot.y = xt.y;                    ob.y = xb.y;
            ot.z = a_tt*xt.z + a_tb*xb.z;   ob.z = a_bt*xt.z + a_bb*xb.z;
            ot.w = xt.w;                    ob.w = xb.w;
        }
        __stwt(&op[fo], ot);
        __stwt(&op[fo + 32*16], ob);
    }

    // ---- Tail: last CTA computes logdet + resets flags for next replay ----
    __threadfence();
    __syncthreads();
    if (tid == 0) {
        int old = atomicAdd(&g_done, 1);
        s_last = (old == 255);
    }
    __syncthreads();
    if (s_last) {
        __threadfence();
        if (tid < Bn) {
            int bb = tid;
            const float off  = off1p[0];
            const float off2 = off2p[0];
            const float off3 = off3p[0];
            float ld = logdet_in[bb];
            #pragma unroll
            for (int gg = 0; gg < 2; ++gg) {
                float4 s = g_S[bb*2 + gg];
                float stt = s.x + off3, stb = s.y + off3;
                float sbt = s.z + off3, sbb = s.w + off3;
                float z = off3;

                float mx  = fmaxf(fmaxf(stt, stb), z);
                float e0  = expf(stt-mx), e1 = expf(stb-mx), ez = expf(z-mx);
                float inv = 1.f / (e0 + e1 + 2.f*ez);
                float a_tt2 = e0*inv + off2 + off1p[0];
                float a_tb2 = e1*inv + off2;

                mx  = fmaxf(fmaxf(sbt, sbb), z);
                e0  = expf(sbt-mx); e1 = expf(sbb-mx); ez = expf(z-mx);
                inv = 1.f / (e0 + e1 + 2.f*ez);
                float a_bt2 = e0*inv + off2;
                float a_bb2 = e1*inv + off2 + off1p[0];

                float det = a_tt2*a_bb2 - a_tb2*a_bt2;
                ld += logf(fabsf(det)) * (float)(Pn*(Pn/2)*Cn);
            }
            if (OUT_ELEMS + bb < out_size) out[OUT_ELEMS + bb] = ld;
        }
        __syncthreads();
        if (tid == 0) { g_flag = 0; g_done = 0; }   // reset for next replay
    }
}

// ---------------------------------------------------------------------------
extern "C" void kernel_launch(void* const* d_in, const int* in_sizes, int n_in,
                              void* d_out, int out_size) {
    const float* x      = (const float*)d_in[0];
    const float* logdet = (const float*)d_in[1];
    const float* Wq1    = (const float*)d_in[2];
    const float* Wq2    = (const float*)d_in[3];
    const float* Wq3    = (const float*)d_in[4];
    const float* Wk1    = (const float*)d_in[5];
    const float* Wk2    = (const float*)d_in[6];
    const float* Wk3    = (const float*)d_in[7];
    const float* off1   = (const float*)d_in[8];
    const float* off2   = (const float*)d_in[9];
    const float* off3   = (const float*)d_in[10];
    float* out = (float*)d_out;

    fused_kernel<<<256, 256>>>(x, logdet, Wq1, Wq2, Wq3, Wk1, Wk2, Wk3,
                               off1, off2, off3, out, out_size);
}